// round 9
// baseline (speedup 1.0000x reference)
#include <cuda_runtime.h>
#include <cuda_fp16.h>
#include <mma.h>
#include <math.h>

using namespace nvcuda;

#define NN 100000
#define EE 1000000
#define RR 3
#define IN_DIM 128
#define OUT_DIM 64

static constexpr int N3 = RR * NN;
static constexpr int E3 = RR * EE;
static constexpr int NB_SCAN = (N3 + 255) / 256;   // 1172

// ---------------- scratch ----------------------------------------------------
__device__ int     g_cnt[N3];
__device__ int     g_rowptr[N3 + 1];
__device__ int     g_col[E3];
__device__ unsigned long long g_lookback[NB_SCAN];
__device__ __half2 g_h2[(size_t)N3 * (OUT_DIM / 2)];
__device__ float   g_alsrc[N3];
__device__ float   g_aldst[N3];
__device__ float   g_hmid[(size_t)NN * OUT_DIM];

// ---------------- CSR build --------------------------------------------------
__global__ void k_hist(const int* __restrict__ e0, const int* __restrict__ e1,
                       const int* __restrict__ e2) {
    int i = blockIdx.x * blockDim.x + threadIdx.x;
    if (i >= E3) return;
    int r = i / EE, e = i - r * EE;
    const int* ei = (r == 0) ? e0 : (r == 1) ? e1 : e2;
    int dst = ei[EE + e];
    atomicAdd(&g_cnt[r * NN + dst], 1);
}

__global__ void k_scan_lookback() {
    __shared__ int sh[256];
    __shared__ int s_prefix;
    int b = blockIdx.x, tid = threadIdx.x;
    int i = b * 256 + tid;
    int v = (i < N3) ? g_cnt[i] : 0;
    sh[tid] = v;
    __syncthreads();
    for (int o = 1; o < 256; o <<= 1) {
        int add = (tid >= o) ? sh[tid - o] : 0;
        __syncthreads();
        sh[tid] += add;
        __syncthreads();
    }
    int total = sh[255];
    if (tid == 0) {
        if (b == 0) {
            *(volatile unsigned long long*)&g_lookback[0] =
                (2ULL << 32) | (unsigned)total;
            s_prefix = 0;
        } else {
            *(volatile unsigned long long*)&g_lookback[b] =
                (1ULL << 32) | (unsigned)total;
            int run = 0, p = b - 1;
            while (true) {
                unsigned long long st = *(volatile unsigned long long*)&g_lookback[p];
                unsigned stt = (unsigned)(st >> 32);
                if (stt == 2u) { run += (int)(st & 0xffffffffu); break; }
                else if (stt == 1u) { run += (int)(st & 0xffffffffu); p--; }
                else { __nanosleep(20); }
            }
            *(volatile unsigned long long*)&g_lookback[b] =
                (2ULL << 32) | (unsigned)(run + total);
            s_prefix = run;
        }
    }
    __syncthreads();
    int excl = s_prefix + sh[tid] - v;
    if (i < N3) { g_rowptr[i] = excl; g_cnt[i] = excl; }
    if (i == 0) g_rowptr[N3] = E3;
}

__global__ void k_scatter(const int* __restrict__ e0, const int* __restrict__ e1,
                          const int* __restrict__ e2) {
    int i = blockIdx.x * blockDim.x + threadIdx.x;
    if (i >= E3) return;
    int r = i / EE, e = i - r * EE;
    const int* ei = (r == 0) ? e0 : (r == 1) ? e1 : e2;
    int src = ei[e];
    int dst = ei[EE + e];
    int pos = atomicAdd(&g_cnt[r * NN + dst], 1);
    g_col[pos] = src;
}

// ---------------- fp16 tensor-core GEMM: 256-row tile, fused logits ----------
// 8 warps; warp w owns rows [w*32, w*32+32) x all 64 cols (2 m-frags x 4 n-frags)
template <int K>
__global__ __launch_bounds__(256) void k_gemm_tc(
        const float* __restrict__ X, const float* __restrict__ W,
        const float* __restrict__ asrc, const float* __restrict__ adst) {
    constexpr int XLDH = 24;                 // halves per X row (16 + 8 pad)
    constexpr int WLDH = 72;                 // halves per W row (64 + 8 pad)
    constexpr int OLD  = 68;                 // floats per O row
    constexpr int W_BYTES = K * WLDH * 2;
    constexpr int X_BYTES = 256 * XLDH * 2;  // 12288
    constexpr int MAIN_BYTES = W_BYTES + X_BYTES;
    constexpr int O_BYTES = 128 * OLD * 4;   // 34816 (epilogue in 2 phases)
    constexpr int BUF_BYTES = (MAIN_BYTES > O_BYTES) ? MAIN_BYTES : O_BYTES;
    __shared__ __align__(16) char buf[BUF_BYTES];
    __half* sW = (__half*)buf;                       // [K][WLDH]
    __half* sX = (__half*)(buf + W_BYTES);           // [256][XLDH]
    float*  sO = (float*)buf;                        // epilogue stage (aliases)

    const int r = blockIdx.z;
    const int row0 = blockIdx.x * 256;
    const int t = threadIdx.x;
    const int w = t >> 5;

    // load whole W[r] into smem as half (once per 256 rows)
    {
        const float4* Wr4 = (const float4*)(W + (size_t)r * K * OUT_DIM);
        for (int i = t; i < K * 16; i += 256) {
            float4 v = Wr4[i];
            int row = i >> 4, c4 = (i & 15) * 4;
            __half2* dstp = (__half2*)&sW[row * WLDH + c4];
            dstp[0] = __float22half2_rn(make_float2(v.x, v.y));
            dstp[1] = __float22half2_rn(make_float2(v.z, v.w));
        }
    }

    wmma::fragment<wmma::accumulator, 16, 16, 16, float> acc[2][4];
#pragma unroll
    for (int mi = 0; mi < 2; mi++)
#pragma unroll
        for (int ct = 0; ct < 4; ct++) wmma::fill_fragment(acc[mi][ct], 0.f);

    for (int kk = 0; kk < K; kk += 16) {
        // stage X chunk [256 x 16] as half
#pragma unroll
        for (int p = 0; p < 4; p++) {
            int idx = t + p * 256;                   // 1024 float4 loads
            int row = idx >> 2, c4 = (idx & 3) * 4;
            int grow = row0 + row;
            float4 v = make_float4(0.f, 0.f, 0.f, 0.f);
            if (grow < NN) v = *(const float4*)(X + (size_t)grow * K + kk + c4);
            __half2* dstp = (__half2*)&sX[row * XLDH + c4];
            dstp[0] = __float22half2_rn(make_float2(v.x, v.y));
            dstp[1] = __float22half2_rn(make_float2(v.z, v.w));
        }
        __syncthreads();
        wmma::fragment<wmma::matrix_a, 16, 16, 16, __half, wmma::row_major> af[2];
#pragma unroll
        for (int mi = 0; mi < 2; mi++)
            wmma::load_matrix_sync(af[mi], &sX[(w * 32 + mi * 16) * XLDH], XLDH);
#pragma unroll
        for (int ct = 0; ct < 4; ct++) {
            wmma::fragment<wmma::matrix_b, 16, 16, 16, __half, wmma::row_major> bf;
            wmma::load_matrix_sync(bf, &sW[kk * WLDH + ct * 16], WLDH);
#pragma unroll
            for (int mi = 0; mi < 2; mi++)
                wmma::mma_sync(acc[mi][ct], af[mi], bf, acc[mi][ct]);
        }
        __syncthreads();
    }

    // epilogue in two 128-row phases (smem stage aliases mainloop buffers)
#pragma unroll
    for (int ph = 0; ph < 2; ph++) {
        if ((w >> 2) == ph) {
#pragma unroll
            for (int mi = 0; mi < 2; mi++)
#pragma unroll
                for (int ct = 0; ct < 4; ct++)
                    wmma::store_matrix_sync(
                        &sO[(w * 32 + mi * 16 - ph * 128) * OLD + ct * 16],
                        acc[mi][ct], OLD, wmma::mem_row_major);
        }
        __syncthreads();
        {
            int row = t >> 1, half = t & 1;
            int grow = row0 + ph * 128 + row;
            float s = 0.f, d = 0.f;
            __half2 hv[16];
            const float* orow = &sO[row * OLD + half * 32];
            const float* av = asrc + r * OUT_DIM + half * 32;
            const float* dv = adst + r * OUT_DIM + half * 32;
#pragma unroll
            for (int j = 0; j < 16; j++) {
                float v0 = orow[2 * j], v1 = orow[2 * j + 1];
                hv[j] = __float22half2_rn(make_float2(v0, v1));
                s = fmaf(v0, __ldg(&av[2 * j]), s);
                s = fmaf(v1, __ldg(&av[2 * j + 1]), s);
                d = fmaf(v0, __ldg(&dv[2 * j]), d);
                d = fmaf(v1, __ldg(&dv[2 * j + 1]), d);
            }
            s += __shfl_xor_sync(0xffffffffu, s, 1);
            d += __shfl_xor_sync(0xffffffffu, d, 1);
            if (grow < NN) {
                float4* dstp = (float4*)(g_h2 + (size_t)(r * NN + grow) * 32 + half * 16);
                const float4* srcp = (const float4*)hv;
#pragma unroll
                for (int q = 0; q < 4; q++) dstp[q] = srcp[q];
                if (half == 0) {
                    g_alsrc[r * NN + grow] = s;
                    g_aldst[r * NN + grow] = d;
                }
            }
        }
        __syncthreads();
    }
}

// ---------------- aggregation: 4 edges/warp-step, 8 features/lane ------------
template <int LAYER>
__global__ void k_agg(const float* __restrict__ bias, float4* __restrict__ out) {
    int d = (blockIdx.x * blockDim.x + threadIdx.x) >> 5;
    int lane = threadIdx.x & 31;
    if (d >= NN) return;
    const int g = lane >> 3;        // edge group 0..3
    const int fl = lane & 7;        // feature slot: floats [fl*8, fl*8+8)
    float facc[8] = {};
#pragma unroll
    for (int r = 0; r < RR; r++) {
        int idx = r * NN + d;
        int s = g_rowptr[idx], e = g_rowptr[idx + 1];
        float ad = g_aldst[idx];
        const float4* hbase = (const float4*)(g_h2 + (size_t)r * NN * 32);
        const float* albase = g_alsrc + r * NN;
        float acc[8] = {};
        float denl = 0.f;
        for (int chunk = s; chunk < e; chunk += 32) {
            int m = e - chunk; if (m > 32) m = 32;
            int srcL = 0; float wL = 0.f;
            if (lane < m) {
                srcL = g_col[chunk + lane];
                float al = albase[srcL] + ad;
                float lr = al > 0.f ? al : 0.2f * al;
                wL = __expf(lr);
            }
            denl += wL;
            for (int base = 0; base < m; base += 4) {
                int src = __shfl_sync(0xffffffffu, srcL, base + g);
                float wv = __shfl_sync(0xffffffffu, wL, base + g);
                // one 16B load = 8 features of edge (base+g)
                uint4 u = *(const uint4*)(hbase + (size_t)src * 8 + fl);
                float2 f0 = __half22float2(*(__half2*)&u.x);
                float2 f1 = __half22float2(*(__half2*)&u.y);
                float2 f2 = __half22float2(*(__half2*)&u.z);
                float2 f3 = __half22float2(*(__half2*)&u.w);
                acc[0] = fmaf(wv, f0.x, acc[0]); acc[1] = fmaf(wv, f0.y, acc[1]);
                acc[2] = fmaf(wv, f1.x, acc[2]); acc[3] = fmaf(wv, f1.y, acc[3]);
                acc[4] = fmaf(wv, f2.x, acc[4]); acc[5] = fmaf(wv, f2.y, acc[5]);
                acc[6] = fmaf(wv, f3.x, acc[6]); acc[7] = fmaf(wv, f3.y, acc[7]);
            }
        }
        float den = denl;
#pragma unroll
        for (int o = 16; o > 0; o >>= 1) den += __shfl_xor_sync(0xffffffffu, den, o);
        if (e > s) {
            float inv = 1.f / den;
#pragma unroll
            for (int k = 0; k < 8; k++) facc[k] = fmaf(acc[k], inv, facc[k]);
        }
    }
    // sum the 4 edge-group partials (groups hold same feature slots)
#pragma unroll
    for (int k = 0; k < 8; k++) {
        facc[k] += __shfl_xor_sync(0xffffffffu, facc[k], 8);
        facc[k] += __shfl_xor_sync(0xffffffffu, facc[k], 16);
    }
    // bias (summed over relations) + mean
#pragma unroll
    for (int k = 0; k < 8; k++) {
        int c = fl * 8 + k;
        float bsum = __ldg(&bias[c]) + __ldg(&bias[OUT_DIM + c]) + __ldg(&bias[2 * OUT_DIM + c]);
        facc[k] = (facc[k] + bsum) * (1.f / 3.f);
    }
    if (LAYER == 1) {
        float sq = 0.f;
#pragma unroll
        for (int k = 0; k < 8; k++) sq = fmaf(facc[k], facc[k], sq);
        // reduce over the 8 feature slots (within group; groups identical)
#pragma unroll
        for (int o = 1; o < 8; o <<= 1) sq += __shfl_xor_sync(0xffffffffu, sq, o);
        float inv = 1.f / fmaxf(sqrtf(sq), 1e-12f);
#pragma unroll
        for (int k = 0; k < 8; k++) facc[k] = fmaxf(facc[k] * inv, 0.f);
    }
    if (g == 0) {
        float4 v0 = make_float4(facc[0], facc[1], facc[2], facc[3]);
        float4 v1 = make_float4(facc[4], facc[5], facc[6], facc[7]);
        out[(size_t)d * 16 + fl * 2]     = v0;
        out[(size_t)d * 16 + fl * 2 + 1] = v1;
    }
}

// ---------------- launch -----------------------------------------------------
extern "C" void kernel_launch(void* const* d_in, const int* in_sizes, int n_in,
                              void* d_out, int out_size) {
    const float* x      = (const float*)d_in[0];
    const int*   ei0    = (const int*)d_in[1];
    const int*   ei1    = (const int*)d_in[2];
    const int*   ei2    = (const int*)d_in[3];
    const float* W1     = (const float*)d_in[4];
    const float* asrc1  = (const float*)d_in[5];
    const float* adst1  = (const float*)d_in[6];
    const float* b1     = (const float*)d_in[7];
    const float* W2     = (const float*)d_in[8];
    const float* asrc2  = (const float*)d_in[9];
    const float* adst2  = (const float*)d_in[10];
    const float* b2     = (const float*)d_in[11];
    float4* out = (float4*)d_out;

    void* cntp;  cudaGetSymbolAddress(&cntp, g_cnt);
    void* lbp;   cudaGetSymbolAddress(&lbp, g_lookback);
    float* hmid; cudaGetSymbolAddress((void**)&hmid, g_hmid);

    cudaMemsetAsync(cntp, 0, (size_t)N3 * sizeof(int));
    cudaMemsetAsync(lbp, 0, (size_t)NB_SCAN * sizeof(unsigned long long));

    k_hist<<<(E3 + 255) / 256, 256>>>(ei0, ei1, ei2);           // launch 1
    k_scan_lookback<<<NB_SCAN, 256>>>();                         // launch 2
    k_scatter<<<(E3 + 255) / 256, 256>>>(ei0, ei1, ei2);        // launch 3

    dim3 ggrid((NN + 255) / 256, 1, RR);
    k_gemm_tc<IN_DIM><<<ggrid, 256>>>(x, W1, asrc1, adst1);     // launch 4 (captured)
    k_agg<1><<<(NN * 32 + 255) / 256, 256>>>(b1, (float4*)hmid);// launch 5

    k_gemm_tc<OUT_DIM><<<ggrid, 256>>>(hmid, W2, asrc2, adst2); // launch 6
    k_agg<2><<<(NN * 32 + 255) / 256, 256>>>(b2, out);          // launch 7
}

// round 10
// speedup vs baseline: 1.1428x; 1.1428x over previous
#include <cuda_runtime.h>
#include <cuda_fp16.h>
#include <mma.h>
#include <math.h>

using namespace nvcuda;

#define NN 100000
#define EE 1000000
#define RR 3
#define IN_DIM 128
#define OUT_DIM 64

static constexpr int N3 = RR * NN;
static constexpr int E3 = RR * EE;
static constexpr int NB_SCAN = (N3 + 255) / 256;   // 1172

// ---------------- scratch ----------------------------------------------------
__device__ int     g_cnt[N3];
__device__ int     g_rowptr[N3 + 1];
__device__ int     g_col[E3];
__device__ unsigned long long g_lookback[NB_SCAN];
__device__ __half2 g_h2[(size_t)N3 * (OUT_DIM / 2)];
__device__ float   g_alsrc[N3];
__device__ float   g_aldst[N3];
__device__ float   g_hmid[(size_t)NN * OUT_DIM];

// ---------------- CSR build --------------------------------------------------
__global__ void k_hist(const int* __restrict__ e0, const int* __restrict__ e1,
                       const int* __restrict__ e2) {
    int i = blockIdx.x * blockDim.x + threadIdx.x;
    if (i >= E3) return;
    int r = i / EE, e = i - r * EE;
    const int* ei = (r == 0) ? e0 : (r == 1) ? e1 : e2;
    int dst = ei[EE + e];
    atomicAdd(&g_cnt[r * NN + dst], 1);
}

__global__ void k_scan_lookback() {
    __shared__ int sh[256];
    __shared__ int s_prefix;
    int b = blockIdx.x, tid = threadIdx.x;
    int i = b * 256 + tid;
    int v = (i < N3) ? g_cnt[i] : 0;
    sh[tid] = v;
    __syncthreads();
    for (int o = 1; o < 256; o <<= 1) {
        int add = (tid >= o) ? sh[tid - o] : 0;
        __syncthreads();
        sh[tid] += add;
        __syncthreads();
    }
    int total = sh[255];
    if (tid == 0) {
        if (b == 0) {
            *(volatile unsigned long long*)&g_lookback[0] =
                (2ULL << 32) | (unsigned)total;
            s_prefix = 0;
        } else {
            *(volatile unsigned long long*)&g_lookback[b] =
                (1ULL << 32) | (unsigned)total;
            int run = 0, p = b - 1;
            while (true) {
                unsigned long long st = *(volatile unsigned long long*)&g_lookback[p];
                unsigned stt = (unsigned)(st >> 32);
                if (stt == 2u) { run += (int)(st & 0xffffffffu); break; }
                else if (stt == 1u) { run += (int)(st & 0xffffffffu); p--; }
                else { __nanosleep(20); }
            }
            *(volatile unsigned long long*)&g_lookback[b] =
                (2ULL << 32) | (unsigned)(run + total);
            s_prefix = run;
        }
    }
    __syncthreads();
    int excl = s_prefix + sh[tid] - v;
    if (i < N3) { g_rowptr[i] = excl; g_cnt[i] = excl; }
    if (i == 0) g_rowptr[N3] = E3;
}

__global__ void k_scatter(const int* __restrict__ e0, const int* __restrict__ e1,
                          const int* __restrict__ e2) {
    int i = blockIdx.x * blockDim.x + threadIdx.x;
    if (i >= E3) return;
    int r = i / EE, e = i - r * EE;
    const int* ei = (r == 0) ? e0 : (r == 1) ? e1 : e2;
    int src = ei[e];
    int dst = ei[EE + e];
    int pos = atomicAdd(&g_cnt[r * NN + dst], 1);
    g_col[pos] = src;
}

// ---------------- fp16 tensor-core GEMM: 256-row tile, fused logits ----------
// 8 warps; warp w owns rows [w*32, w*32+32) x all 64 cols (2 m-frags x 4 n-frags)
template <int K>
__global__ __launch_bounds__(256) void k_gemm_tc(
        const float* __restrict__ X, const float* __restrict__ W,
        const float* __restrict__ asrc, const float* __restrict__ adst) {
    constexpr int XLDH = 24;                 // halves per X row (16 + 8 pad)
    constexpr int WLDH = 72;                 // halves per W row (64 + 8 pad)
    constexpr int OLD  = 68;                 // floats per O row
    constexpr int W_BYTES = K * WLDH * 2;
    constexpr int X_BYTES = 256 * XLDH * 2;  // 12288
    constexpr int MAIN_BYTES = W_BYTES + X_BYTES;
    constexpr int O_BYTES = 128 * OLD * 4;   // 34816 (epilogue in 2 phases)
    constexpr int BUF_BYTES = (MAIN_BYTES > O_BYTES) ? MAIN_BYTES : O_BYTES;
    __shared__ __align__(16) char buf[BUF_BYTES];
    __half* sW = (__half*)buf;                       // [K][WLDH]
    __half* sX = (__half*)(buf + W_BYTES);           // [256][XLDH]
    float*  sO = (float*)buf;                        // epilogue stage (aliases)

    const int r = blockIdx.z;
    const int row0 = blockIdx.x * 256;
    const int t = threadIdx.x;
    const int w = t >> 5;

    // load whole W[r] into smem as half (once per 256 rows)
    {
        const float4* Wr4 = (const float4*)(W + (size_t)r * K * OUT_DIM);
        for (int i = t; i < K * 16; i += 256) {
            float4 v = Wr4[i];
            int row = i >> 4, c4 = (i & 15) * 4;
            __half2* dstp = (__half2*)&sW[row * WLDH + c4];
            dstp[0] = __float22half2_rn(make_float2(v.x, v.y));
            dstp[1] = __float22half2_rn(make_float2(v.z, v.w));
        }
    }

    wmma::fragment<wmma::accumulator, 16, 16, 16, float> acc[2][4];
#pragma unroll
    for (int mi = 0; mi < 2; mi++)
#pragma unroll
        for (int ct = 0; ct < 4; ct++) wmma::fill_fragment(acc[mi][ct], 0.f);

    for (int kk = 0; kk < K; kk += 16) {
        // stage X chunk [256 x 16] as half
#pragma unroll
        for (int p = 0; p < 4; p++) {
            int idx = t + p * 256;                   // 1024 float4 loads
            int row = idx >> 2, c4 = (idx & 3) * 4;
            int grow = row0 + row;
            float4 v = make_float4(0.f, 0.f, 0.f, 0.f);
            if (grow < NN) v = *(const float4*)(X + (size_t)grow * K + kk + c4);
            __half2* dstp = (__half2*)&sX[row * XLDH + c4];
            dstp[0] = __float22half2_rn(make_float2(v.x, v.y));
            dstp[1] = __float22half2_rn(make_float2(v.z, v.w));
        }
        __syncthreads();
        wmma::fragment<wmma::matrix_a, 16, 16, 16, __half, wmma::row_major> af[2];
#pragma unroll
        for (int mi = 0; mi < 2; mi++)
            wmma::load_matrix_sync(af[mi], &sX[(w * 32 + mi * 16) * XLDH], XLDH);
#pragma unroll
        for (int ct = 0; ct < 4; ct++) {
            wmma::fragment<wmma::matrix_b, 16, 16, 16, __half, wmma::row_major> bf;
            wmma::load_matrix_sync(bf, &sW[kk * WLDH + ct * 16], WLDH);
#pragma unroll
            for (int mi = 0; mi < 2; mi++)
                wmma::mma_sync(acc[mi][ct], af[mi], bf, acc[mi][ct]);
        }
        __syncthreads();
    }

    // epilogue in two 128-row phases (smem stage aliases mainloop buffers)
#pragma unroll
    for (int ph = 0; ph < 2; ph++) {
        if ((w >> 2) == ph) {
#pragma unroll
            for (int mi = 0; mi < 2; mi++)
#pragma unroll
                for (int ct = 0; ct < 4; ct++)
                    wmma::store_matrix_sync(
                        &sO[(w * 32 + mi * 16 - ph * 128) * OLD + ct * 16],
                        acc[mi][ct], OLD, wmma::mem_row_major);
        }
        __syncthreads();
        {
            int row = t >> 1, half = t & 1;
            int grow = row0 + ph * 128 + row;
            float s = 0.f, d = 0.f;
            __half2 hv[16];
            const float* orow = &sO[row * OLD + half * 32];
            const float* av = asrc + r * OUT_DIM + half * 32;
            const float* dv = adst + r * OUT_DIM + half * 32;
#pragma unroll
            for (int j = 0; j < 16; j++) {
                float v0 = orow[2 * j], v1 = orow[2 * j + 1];
                hv[j] = __float22half2_rn(make_float2(v0, v1));
                s = fmaf(v0, __ldg(&av[2 * j]), s);
                s = fmaf(v1, __ldg(&av[2 * j + 1]), s);
                d = fmaf(v0, __ldg(&dv[2 * j]), d);
                d = fmaf(v1, __ldg(&dv[2 * j + 1]), d);
            }
            s += __shfl_xor_sync(0xffffffffu, s, 1);
            d += __shfl_xor_sync(0xffffffffu, d, 1);
            if (grow < NN) {
                float4* dstp = (float4*)(g_h2 + (size_t)(r * NN + grow) * 32 + half * 16);
                const float4* srcp = (const float4*)hv;
#pragma unroll
                for (int q = 0; q < 4; q++) dstp[q] = srcp[q];
                if (half == 0) {
                    g_alsrc[r * NN + grow] = s;
                    g_aldst[r * NN + grow] = d;
                }
            }
        }
        __syncthreads();
    }
}

// ---------------- aggregation (R8 serial form — proven fastest) --------------
template <int LAYER>
__global__ void k_agg(const float* __restrict__ bias, float2* __restrict__ out) {
    int d = (blockIdx.x * blockDim.x + threadIdx.x) >> 5;
    int lane = threadIdx.x & 31;
    if (d >= NN) return;
    float t0 = 0.f, t1 = 0.f;
#pragma unroll
    for (int r = 0; r < RR; r++) {
        int idx = r * NN + d;
        int s = g_rowptr[idx], e = g_rowptr[idx + 1];
        float ad = g_aldst[idx];
        float acc0 = 0.f, acc1 = 0.f, den = 0.f;
        const __half2* hbase = g_h2 + (size_t)r * NN * (OUT_DIM / 2);
        const float* albase = g_alsrc + r * NN;
        for (int j = s; j < e; j++) {
            int src = g_col[j];
            float al = albase[src] + ad;
            float lr = al > 0.f ? al : 0.2f * al;
            float w = __expf(lr);
            den += w;
            float2 hv = __half22float2(hbase[(size_t)src * (OUT_DIM / 2) + lane]);
            acc0 = fmaf(w, hv.x, acc0);
            acc1 = fmaf(w, hv.y, acc1);
        }
        if (e > s) {
            float inv = 1.f / den;
            t0 = fmaf(acc0, inv, t0);
            t1 = fmaf(acc1, inv, t1);
        }
        t0 += __ldg(&bias[r * OUT_DIM + 2 * lane]);
        t1 += __ldg(&bias[r * OUT_DIM + 2 * lane + 1]);
    }
    t0 *= (1.f / 3.f);
    t1 *= (1.f / 3.f);
    if (LAYER == 1) {
        float sq = t0 * t0 + t1 * t1;
#pragma unroll
        for (int o = 16; o > 0; o >>= 1) sq += __shfl_xor_sync(0xffffffffu, sq, o);
        float inv = 1.f / fmaxf(sqrtf(sq), 1e-12f);
        t0 = fmaxf(t0 * inv, 0.f);
        t1 = fmaxf(t1 * inv, 0.f);
    }
    out[(size_t)d * (OUT_DIM / 2) + lane] = make_float2(t0, t1);
}

// ---------------- launch -----------------------------------------------------
extern "C" void kernel_launch(void* const* d_in, const int* in_sizes, int n_in,
                              void* d_out, int out_size) {
    const float* x      = (const float*)d_in[0];
    const int*   ei0    = (const int*)d_in[1];
    const int*   ei1    = (const int*)d_in[2];
    const int*   ei2    = (const int*)d_in[3];
    const float* W1     = (const float*)d_in[4];
    const float* asrc1  = (const float*)d_in[5];
    const float* adst1  = (const float*)d_in[6];
    const float* b1     = (const float*)d_in[7];
    const float* W2     = (const float*)d_in[8];
    const float* asrc2  = (const float*)d_in[9];
    const float* adst2  = (const float*)d_in[10];
    const float* b2     = (const float*)d_in[11];
    float2* out = (float2*)d_out;

    void* cntp;  cudaGetSymbolAddress(&cntp, g_cnt);
    void* lbp;   cudaGetSymbolAddress(&lbp, g_lookback);
    float* hmid; cudaGetSymbolAddress((void**)&hmid, g_hmid);

    cudaMemsetAsync(cntp, 0, (size_t)N3 * sizeof(int));
    cudaMemsetAsync(lbp, 0, (size_t)NB_SCAN * sizeof(unsigned long long));

    k_hist<<<(E3 + 255) / 256, 256>>>(ei0, ei1, ei2);           // launch 1
    k_scan_lookback<<<NB_SCAN, 256>>>();                         // launch 2
    k_scatter<<<(E3 + 255) / 256, 256>>>(ei0, ei1, ei2);        // launch 3

    dim3 ggrid((NN + 255) / 256, 1, RR);
    k_gemm_tc<IN_DIM><<<ggrid, 256>>>(x, W1, asrc1, adst1);     // launch 4 (captured)
    k_agg<1><<<(NN * 32 + 255) / 256, 256>>>(b1, (float2*)hmid);// launch 5

    k_gemm_tc<OUT_DIM><<<ggrid, 256>>>(hmid, W2, asrc2, adst2); // launch 6
    k_agg<2><<<(NN * 32 + 255) / 256, 256>>>(b2, out);          // launch 7
}